// round 3
// baseline (speedup 1.0000x reference)
#include <cuda_runtime.h>
#include <math.h>

#define NMAX 50000
#define EMAX 1600000
#define H 64

// ---------------- scratch (static device globals; no allocation) ----------------
__device__ int   g_deg[NMAX];
__device__ int   g_rowcnt[NMAX];
__device__ int   g_rowptr[NMAX + 1];
__device__ int   g_fill[NMAX];
__device__ float g_dinv[NMAX];
__device__ int   g_colidx[EMAX];
__device__ float g_val[EMAX];
__device__ float g_h[NMAX * H];
__device__ float g_h0[NMAX * H];
__device__ float g_tmp[NMAX * H];
__device__ float g_A[NMAX * H];
__device__ float g_B[NMAX * H];

// ---------------- setup kernels ----------------
__global__ void k_init(int n) {
    int i = blockIdx.x * blockDim.x + threadIdx.x;
    if (i < n) { g_deg[i] = 1; g_rowcnt[i] = 0; }
}

__global__ void k_count(const int* __restrict__ ei, int e_cnt) {
    int e = blockIdx.x * blockDim.x + threadIdx.x;
    if (e < e_cnt) {
        atomicAdd(&g_deg[ei[e_cnt + e]], 1);   // deg over col (edge_index[1])
        atomicAdd(&g_rowcnt[ei[e]], 1);        // CSR histogram over row (edge_index[0])
    }
}

__global__ void k_dinv(int n) {
    int i = blockIdx.x * blockDim.x + threadIdx.x;
    if (i < n) g_dinv[i] = rsqrtf((float)g_deg[i]);
}

// single-block exclusive scan over g_rowcnt -> g_rowptr (+ copy to g_fill)
__global__ void k_scan(int n, int total) {
    __shared__ int wsum[32];
    __shared__ int s_carry;
    int tid = threadIdx.x, lane = tid & 31, wid = tid >> 5;
    if (tid == 0) s_carry = 0;
    __syncthreads();
    for (int base = 0; base < n; base += 1024) {
        int i = base + tid;
        int v = (i < n) ? g_rowcnt[i] : 0;
        int x = v;
        #pragma unroll
        for (int o = 1; o < 32; o <<= 1) {
            int y = __shfl_up_sync(0xffffffffu, x, o);
            if (lane >= o) x += y;
        }
        if (lane == 31) wsum[wid] = x;
        __syncthreads();
        if (wid == 0) {
            int w = wsum[lane];
            #pragma unroll
            for (int o = 1; o < 32; o <<= 1) {
                int y = __shfl_up_sync(0xffffffffu, w, o);
                if (lane >= o) w += y;
            }
            wsum[lane] = w;
        }
        __syncthreads();
        int carry = s_carry;
        int excl = carry + (x - v) + (wid ? wsum[wid - 1] : 0);
        if (i < n) { g_rowptr[i] = excl; g_fill[i] = excl; }
        __syncthreads();
        if (tid == 1023) s_carry = excl + v;
        __syncthreads();
    }
    if (tid == 0) g_rowptr[n] = total;
}

__global__ void k_csr_fill(const int* __restrict__ ei, int e_cnt) {
    int e = blockIdx.x * blockDim.x + threadIdx.x;
    if (e < e_cnt) {
        int r = ei[e], c = ei[e_cnt + e];
        int p = atomicAdd(&g_fill[r], 1);
        g_colidx[p] = c;
        g_val[p] = g_dinv[r] * g_dinv[c];
    }
}

// ---------------- dense 64x64 GEMM: out = f(cs*in + cw*(in@W) + bias) ----------------
// warp-per-row, 8 rows per warp, W staged in smem, input row broadcast via shfl.
__global__ void k_gemm64(const float* __restrict__ in, const float* __restrict__ W,
                         const float* __restrict__ bias, float* __restrict__ out,
                         float* __restrict__ out2, float cs, float cw, int do_relu, int n) {
    __shared__ float sW[64 * 64];
    for (int i = threadIdx.x; i < 4096; i += blockDim.x) sW[i] = W[i];
    __syncthreads();
    int lane = threadIdx.x & 31, warp = threadIdx.x >> 5;
    const float2* in2 = (const float2*)in;
    const float2* sW2 = (const float2*)sW;
    float bx = 0.f, by = 0.f;
    if (bias) { float2 b = ((const float2*)bias)[lane]; bx = b.x; by = b.y; }
    int base = (blockIdx.x * 8 + warp) * 8;
    for (int rr = 0; rr < 8; rr++) {
        int row = base + rr;
        if (row >= n) break;
        float2 rv = in2[row * 32 + lane];
        float a0 = 0.f, a1 = 0.f;
        #pragma unroll
        for (int s = 0; s < 32; s++) {
            float vx = __shfl_sync(0xffffffffu, rv.x, s);
            float vy = __shfl_sync(0xffffffffu, rv.y, s);
            float2 w0 = sW2[(2 * s) * 32 + lane];
            float2 w1 = sW2[(2 * s + 1) * 32 + lane];
            a0 = fmaf(vx, w0.x, fmaf(vy, w1.x, a0));
            a1 = fmaf(vx, w0.y, fmaf(vy, w1.y, a1));
        }
        float o0 = cs * rv.x + cw * a0 + bx;
        float o1 = cs * rv.y + cw * a1 + by;
        if (do_relu) { o0 = fmaxf(o0, 0.f); o1 = fmaxf(o1, 0.f); }
        float2 o = make_float2(o0, o1);
        ((float2*)out)[row * 32 + lane] = o;
        if (out2) ((float2*)out2)[row * 32 + lane] = o;
    }
}

// ---------------- SpMM + GCN2 mix: g_tmp = 0.9*(A_hat @ h) + 0.1*h0 ----------------
// warp per node, lane owns 2 features (float2); self-loop handled analytically.
__global__ void k_spmm(int n) {
    int lane = threadIdx.x & 31, warp = threadIdx.x >> 5;
    int node = blockIdx.x * 8 + warp;
    if (node >= n) return;
    const float2* h2 = (const float2*)g_h;
    float di = g_dinv[node];
    float2 hv = h2[node * 32 + lane];
    float ax = di * di * hv.x;
    float ay = di * di * hv.y;
    int e0 = g_rowptr[node], e1 = g_rowptr[node + 1];
    for (int e = e0; e < e1; e++) {
        int c = g_colidx[e];
        float v = g_val[e];
        float2 xv = h2[c * 32 + lane];
        ax = fmaf(v, xv.x, ax);
        ay = fmaf(v, xv.y, ay);
    }
    float2 h0v = ((const float2*)g_h0)[node * 32 + lane];
    float2 m = make_float2(0.9f * ax + 0.1f * h0v.x, 0.9f * ay + 0.1f * h0v.y);
    ((float2*)g_tmp)[node * 32 + lane] = m;
}

// ---------------- edge MLP: z=A[src]+B[dst]+b1 -> LN -> relu -> @W2+b2 ----------------
__global__ void k_edge(const int* __restrict__ ei,
                       const float* __restrict__ b1, const float* __restrict__ ln_g,
                       const float* __restrict__ ln_b, const float* __restrict__ W2,
                       const float* __restrict__ b2, float* __restrict__ out, int e_cnt) {
    const int EPW = 16;
    int lane = threadIdx.x & 31, warp = threadIdx.x >> 5;
    int base = (blockIdx.x * 8 + warp) * EPW;
    float w2a[10], w2b[10];
    #pragma unroll
    for (int c = 0; c < 10; c++) {
        w2a[c] = W2[(2 * lane) * 10 + c];
        w2b[c] = W2[(2 * lane + 1) * 10 + c];
    }
    float2 b1v = ((const float2*)b1)[lane];
    float2 gv  = ((const float2*)ln_g)[lane];
    float2 bv  = ((const float2*)ln_b)[lane];
    float myb2 = (lane < 10) ? b2[lane] : 0.f;
    const float2* A2 = (const float2*)g_A;
    const float2* B2 = (const float2*)g_B;
    for (int t = 0; t < EPW; t++) {
        int e = base + t;
        if (e >= e_cnt) return;
        int s = ei[e], d = ei[e_cnt + e];
        float2 za = A2[s * 32 + lane];
        float2 zb = B2[d * 32 + lane];
        float zx = za.x + zb.x + b1v.x;
        float zy = za.y + zb.y + b1v.y;
        float sum = zx + zy;
        float sq = zx * zx + zy * zy;
        #pragma unroll
        for (int o = 16; o; o >>= 1) {
            sum += __shfl_xor_sync(0xffffffffu, sum, o);
            sq  += __shfl_xor_sync(0xffffffffu, sq, o);
        }
        float mu = sum * (1.f / 64.f);
        float var = sq * (1.f / 64.f) - mu * mu;
        float inv = rsqrtf(var + 1e-5f);
        zx = fmaxf((zx - mu) * inv * gv.x + bv.x, 0.f);
        zy = fmaxf((zy - mu) * inv * gv.y + bv.y, 0.f);
        float res = 0.f;
        #pragma unroll
        for (int c = 0; c < 10; c++) {
            float p = zx * w2a[c] + zy * w2b[c];
            #pragma unroll
            for (int o = 16; o; o >>= 1) p += __shfl_xor_sync(0xffffffffu, p, o);
            if (lane == c) res = p + myb2;
        }
        if (lane < 10) out[e * 10 + lane] = res;
    }
}

// ---------------- host launcher ----------------
extern "C" void kernel_launch(void* const* d_in, const int* in_sizes, int n_in,
                              void* d_out, int out_size) {
    const float* x     = (const float*)d_in[0];
    const float* W_lin = (const float*)d_in[1];
    const float* b_lin = (const float*)d_in[2];
    const float* Ws    = (const float*)d_in[3];
    const float* W1    = (const float*)d_in[4];
    const float* b1    = (const float*)d_in[5];
    const float* ln_g  = (const float*)d_in[6];
    const float* ln_b  = (const float*)d_in[7];
    const float* W2    = (const float*)d_in[8];
    const float* b2    = (const float*)d_in[9];
    const int*   ei    = (const int*)d_in[10];
    float* out = (float*)d_out;

    int n = in_sizes[0] / H;        // 50000
    int e = in_sizes[10] / 2;       // 1600000

    float *p_h, *p_h0, *p_tmp, *p_A, *p_B;
    cudaGetSymbolAddress((void**)&p_h, g_h);
    cudaGetSymbolAddress((void**)&p_h0, g_h0);
    cudaGetSymbolAddress((void**)&p_tmp, g_tmp);
    cudaGetSymbolAddress((void**)&p_A, g_A);
    cudaGetSymbolAddress((void**)&p_B, g_B);

    // CSR + normalization build
    k_init<<<(n + 255) / 256, 256>>>(n);
    k_count<<<(e + 255) / 256, 256>>>(ei, e);
    k_dinv<<<(n + 255) / 256, 256>>>(n);
    k_scan<<<1, 1024>>>(n, e);
    k_csr_fill<<<(e + 255) / 256, 256>>>(ei, e);

    int ggrid = (n + 63) / 64;
    // h = relu(x @ W_lin + b_lin); h0 = h
    k_gemm64<<<ggrid, 256>>>(x, W_lin, b_lin, p_h, p_h0, 0.f, 1.f, 1, n);

    for (int l = 0; l < 8; l++) {
        float beta = (float)log(0.5 / (double)(l + 1) + 1.0);
        k_spmm<<<(n + 7) / 8, 256>>>(n);
        // h = relu((1-beta)*mix + beta*(mix @ Ws[l]))
        k_gemm64<<<ggrid, 256>>>(p_tmp, Ws + l * 4096, nullptr, p_h, nullptr,
                                 1.0f - beta, beta, 1, n);
    }

    // A = h @ W1[:64], B = h @ W1[64:]
    k_gemm64<<<ggrid, 256>>>(p_h, W1, nullptr, p_A, nullptr, 0.f, 1.f, 0, n);
    k_gemm64<<<ggrid, 256>>>(p_h, W1 + 64 * 64, nullptr, p_B, nullptr, 0.f, 1.f, 0, n);

    // per-edge MLP head
    k_edge<<<(e + 127) / 128, 256>>>(ei, b1, ln_g, ln_b, W2, b2, out, e);
}